// round 7
// baseline (speedup 1.0000x reference)
#include <cuda_runtime.h>

#define CH 4
#define HDIM 1025
#define WDIM 1024
#define NTOT (CH*HDIM*WDIM)
#define STRIDE_T 1028
#define NT_T (CH*WDIM*STRIDE_T)
#define SEG 64
#define BS 128

// scratch (allocation-free rule: __device__ globals; zero-initialized)
__device__ __align__(16) float g_ST[NT_T];     // S transposed: (4, 1024, STRIDE_T), cols 0..1024 valid
__device__ __align__(16) float g_harm[NTOT];   // harmonic median, NATURAL layout (4,1025,1024)

__device__ __forceinline__ float finf() { return __int_as_float(0x7f800000); }

__device__ __forceinline__ void cas(float& a, float& b) {
    float lo = fminf(a, b);
    float hi = fmaxf(a, b);
    a = lo; b = hi;
}

// Batcher odd-even mergesort, n=32, fully unrolled -> registers
__device__ __forceinline__ void sort32(float* a) {
#pragma unroll
    for (int p = 1; p < 32; p <<= 1)
#pragma unroll
        for (int k = p; k >= 1; k >>= 1)
#pragma unroll
            for (int j = k & (p - 1); j + k < 32; j += 2 * k)
#pragma unroll
                for (int i = 0; i < k; ++i)
                    if (i + j + k < 32)
                        if (((i + j) / (2 * p)) == ((i + j + k) / (2 * p)))
                            cas(a[i + j], a[i + j + k]);
}

// Branch-free slide of a sorted 31-window: delete cxo (present), insert cxi.
// d[i] = (v[i]<cxo) ? v[i] : v[i+1]; new[i] = min(max(d[i-1],cxi), d[i]).
__device__ __forceinline__ void slide31(float* v, float cxo, float cxi) {
    float dc = (v[30] < cxo) ? v[30] : finf();
#pragma unroll
    for (int i = 30; i >= 1; --i) {
        float dp = (v[i - 1] < cxo) ? v[i - 1] : v[i];
        v[i] = fminf(fmaxf(dp, cxi), dc);
        dc = dp;
    }
    v[0] = fminf(cxi, dc);
}

// ---------------- transpose: S (4,1025,1024) -> ST (4,1024,STRIDE_T) ----------------
__global__ void __launch_bounds__(256) transpose_kernel(const float* __restrict__ S) {
    __shared__ float tile[32][33];
    int ch = blockIdx.z;
    int h0 = blockIdx.y * 32;
    int w0 = blockIdx.x * 32;
    int tx = threadIdx.x, ty = threadIdx.y;   // (32, 8)
    const float* Sp = S + (size_t)ch * HDIM * WDIM;
#pragma unroll
    for (int i = 0; i < 4; ++i) {
        int h = h0 + ty + i * 8;
        if (h < HDIM) tile[ty + i * 8][tx] = Sp[(size_t)h * WDIM + (w0 + tx)];
    }
    __syncthreads();
    float* STp = g_ST + (size_t)ch * WDIM * STRIDE_T;
#pragma unroll
    for (int i = 0; i < 4; ++i) {
        int w = w0 + ty + i * 8;
        int h = h0 + tx;
        if (h < HDIM) STp[(size_t)w * STRIDE_T + h] = tile[tx][ty + i * 8];
    }
}

// ---------------- harmonic: column median on ST, output in NATURAL layout --------------
// Block: 128 consecutive h (threads), one 64-wide w segment, one channel.
// Outputs staged in a 16x129 smem tile, flushed transposed (coalesced) every 16 slides.
__global__ void __launch_bounds__(BS, 6) colmed_h_kernel() {
    __shared__ float ot[16][BS + 1];
    int ch = blockIdx.z;
    int seg = blockIdx.y;                  // 0..15
    int h0 = blockIdx.x * BS;              // 0,128,...,1024
    int tid = threadIdx.x;
    int h = h0 + tid;
    bool valid = (h < HDIM);
    int hc = valid ? h : 0;
    const float* in = g_ST + (size_t)ch * WDIM * STRIDE_T + hc;
    int r0 = seg * SEG;                    // w start; all segments full (1024 % 64 == 0)

    float v[32];
#pragma unroll
    for (int i = 0; i < 31; ++i) {
        int p = r0 - 15 + i;
        float x = 0.f;
        if (p >= 0 && p < WDIM) x = in[(size_t)p * STRIDE_T];
        v[i] = x;
    }
    v[31] = finf();
    sort32(v);

    float xo = (r0 >= 15) ? in[(size_t)(r0 - 15) * STRIDE_T] : 0.f;
    float xi = (r0 + 16 < WDIM) ? in[(size_t)(r0 + 16) * STRIDE_T] : 0.f;

    float* outBase = g_harm + (size_t)ch * HDIM * WDIM;
#pragma unroll 1
    for (int chunk = 0; chunk < SEG / 16; ++chunk) {
#pragma unroll 2
        for (int s = 0; s < 16; ++s) {
            int r = r0 + chunk * 16 + s;
            ot[s][tid] = v[15];
            float cxo = xo, cxi = xi;
            int ro = r - 14, ri = r + 17;
            xo = (ro >= 0) ? in[(size_t)ro * STRIDE_T] : 0.f;
            xi = (ri < WDIM) ? in[(size_t)ri * STRIDE_T] : 0.f;
            slide31(v, cxo, cxi);
        }
        __syncthreads();
        // flush: 16 w-rows x 128 h-cols -> natural layout (half-warp = 16 consecutive w)
        int wl = tid & 15, hl = tid >> 4;  // hl 0..7
#pragma unroll
        for (int b = 0; b < 16; ++b) {
            int hh = h0 + hl + b * 8;
            if (hh < HDIM)
                outBase[(size_t)hh * WDIM + (r0 + chunk * 16 + wl)] = ot[wl][hl + b * 8];
        }
        __syncthreads();
    }
}

// ---------------- percussive colmed + fused softmask --------------
// Thread at column w walks h; perc = v[15]; loads S and harm (both natural, coalesced,
// L2-hot) while the ~124-instr slide hides their latency; writes both outputs.
__global__ void __launch_bounds__(BS, 6) colmed_pm_kernel(const float* __restrict__ S,
                                                          float* __restrict__ outA,
                                                          float* __restrict__ outB) {
    int ch = blockIdx.z;
    int seg = blockIdx.y;                  // 0..16
    int w = blockIdx.x * BS + threadIdx.x; // 0..1023
    size_t chOff = (size_t)ch * HDIM * WDIM;
    const float* in = S + chOff + w;
    const float* hm = g_harm + chOff + w;
    int r0 = seg * SEG;
    int r1 = min(r0 + SEG, HDIM);

    float v[32];
#pragma unroll
    for (int i = 0; i < 31; ++i) {
        int p = r0 - 15 + i;
        float x = 0.f;
        if (p >= 0 && p < HDIM) x = in[(size_t)p * WDIM];
        v[i] = x;
    }
    v[31] = finf();
    sort32(v);

    float xo = (r0 >= 15) ? in[(size_t)(r0 - 15) * WDIM] : 0.f;
    float xi = (r0 + 16 < HDIM) ? in[(size_t)(r0 + 16) * WDIM] : 0.f;

#pragma unroll 2
    for (int r = r0; r < r1; ++r) {
        float pval = v[15];
        // issue epilogue loads early; slide math hides their latency
        float sv = in[(size_t)r * WDIM];
        float hv = hm[(size_t)r * WDIM];
        float cxo = xo, cxi = xi;
        int ro = r - 14, ri = r + 17;
        xo = (ro >= 0) ? in[(size_t)ro * WDIM] : 0.f;
        xi = (ri < HDIM) ? in[(size_t)ri * WDIM] : 0.f;
        slide31(v, cxo, cxi);
        // softmask: mask_h = h^2/(h^2+p^2), mask_p = p^2/(h^2+p^2)
        float hh = hv * hv, pp = pval * pval;
        float rcp = __fdividef(1.0f, fmaxf(hh + pp, 1e-30f));
        size_t idx = chOff + (size_t)r * WDIM + w;
        outA[idx] = sv * hh * rcp;
        outB[idx] = sv * pp * rcp;
    }
}

extern "C" void kernel_launch(void* const* d_in, const int* in_sizes, int n_in,
                              void* d_out, int out_size) {
    const float* S = (const float*)d_in[0];
    float* out = (float*)d_out;

    // 1) transpose S into ST (padded stride)
    transpose_kernel<<<dim3(WDIM / 32, (HDIM + 31) / 32, CH), dim3(32, 8)>>>(S);

    // 2) harmonic medians (ST -> g_harm natural layout)
    colmed_h_kernel<<<dim3((HDIM + BS - 1) / BS, WDIM / SEG, CH), BS>>>();

    // 3) percussive medians + softmask + both outputs
    colmed_pm_kernel<<<dim3(WDIM / BS, (HDIM + SEG - 1) / SEG, CH), BS>>>(S, out, out + NTOT);
}

// round 10
// speedup vs baseline: 1.1816x; 1.1816x over previous
#include <cuda_runtime.h>

#define CH 4
#define HDIM 1025
#define WDIM 1024
#define NTOT (CH*HDIM*WDIM)
#define STRIDE_T 1028
#define NT_T (CH*WDIM*STRIDE_T)
#define SEG 64
#define BS 128

// fused colmed grid constants
#define NJOBS_H (16 * CH * HDIM)            /* 16 segs * 4 ch * 1025 cols = 65600 */
#define BLOCKS_H ((NJOBS_H + BS - 1) / BS)  /* 513 */
#define NJOBS_P (17 * CH * WDIM)            /* 17 segs * 4 ch * 1024 cols = 69632 */
#define BLOCKS_P ((NJOBS_P + BS - 1) / BS)  /* 544 */

// scratch (allocation-free rule: __device__ globals)
__device__ __align__(16) float g_ST[NT_T];      // S transposed: (4, 1024, STRIDE_T), cols 0..1024 valid
__device__ __align__(16) float g_harmT[NT_T];   // harmonic median, transposed+padded layout
__device__ __align__(16) float g_perc[NTOT];    // percussive median, natural layout

__device__ __forceinline__ float finf() { return __int_as_float(0x7f800000); }

__device__ __forceinline__ void cas(float& a, float& b) {
    float lo = fminf(a, b);
    float hi = fmaxf(a, b);
    a = lo; b = hi;
}

// Batcher odd-even mergesort, n=32, fully unrolled -> registers
__device__ __forceinline__ void sort32(float* a) {
#pragma unroll
    for (int p = 1; p < 32; p <<= 1)
#pragma unroll
        for (int k = p; k >= 1; k >>= 1)
#pragma unroll
            for (int j = k & (p - 1); j + k < 32; j += 2 * k)
#pragma unroll
                for (int i = 0; i < k; ++i)
                    if (i + j + k < 32)
                        if (((i + j) / (2 * p)) == ((i + j + k) / (2 * p)))
                            cas(a[i + j], a[i + j + k]);
}

// ---------------- transpose v2: S (4,1025,1024) -> ST (4,1024,STRIDE_T) ----------------
// 64x64 tile per 256-thread block; float4 on both global sides; scalar smem staging.
__global__ void __launch_bounds__(256) transpose_kernel(const float* __restrict__ S) {
    __shared__ float tile[64 * 65];          // [w_local][h_local], stride 65
    int ch = blockIdx.z;
    int h0 = blockIdx.y * 64;
    int w0 = blockIdx.x * 64;
    int t = threadIdx.x;
    int fc = t & 15;                          // float4 column 0..15
    int rr = t >> 4;                          // 0..15
    const float* Sp = S + (size_t)ch * HDIM * WDIM;

#pragma unroll
    for (int k = 0; k < 4; ++k) {
        int r = rr + 16 * k;                  // h_local 0..63
        int h = h0 + r;
        float4 v = make_float4(0.f, 0.f, 0.f, 0.f);
        if (h < HDIM) v = *(const float4*)(Sp + (size_t)h * WDIM + w0 + 4 * fc);
        tile[(4 * fc + 0) * 65 + r] = v.x;
        tile[(4 * fc + 1) * 65 + r] = v.y;
        tile[(4 * fc + 2) * 65 + r] = v.z;
        tile[(4 * fc + 3) * 65 + r] = v.w;
    }
    __syncthreads();

    float* STp = g_ST + (size_t)ch * WDIM * STRIDE_T;
    if (h0 + 4 * fc <= 1024) {                // keep all writes inside each padded row
#pragma unroll
        for (int k = 0; k < 4; ++k) {
            int wr = rr + 16 * k;             // w_local
            float4 o;
            o.x = tile[wr * 65 + 4 * fc + 0];
            o.y = tile[wr * 65 + 4 * fc + 1];
            o.z = tile[wr * 65 + 4 * fc + 2];
            o.w = tile[wr * 65 + 4 * fc + 3];
            *(float4*)(STp + (size_t)(w0 + wr) * STRIDE_T + h0 + 4 * fc) = o;
        }
    }
}

// ---------------- sliding sorted-window median-31 over one column segment --------------
// Window v[0..30] sorted ascending (v[31] = INF sentinel for the prologue sort).
// Slide = branch-free parallel replace: d[i] = (v[i]<xo ? v[i] : v[i+1]);
// new[i] = min(max(d[i-1], xi), d[i]).
template<int R, int STRIDE>
__device__ __forceinline__ void colmed_run(const float* __restrict__ in,
                                           float* __restrict__ out,
                                           int r0, int r1) {
    float v[32];
#pragma unroll
    for (int i = 0; i < 31; ++i) {
        int p = r0 - 15 + i;
        float x = 0.f;
        if (p >= 0 && p < R) x = in[(size_t)p * STRIDE];
        v[i] = x;
    }
    v[31] = finf();
    sort32(v);

    float xo = (r0 >= 15) ? in[(size_t)(r0 - 15) * STRIDE] : 0.f;
    float xi = (r0 + 16 < R) ? in[(size_t)(r0 + 16) * STRIDE] : 0.f;

#pragma unroll 2
    for (int r = r0; r < r1; ++r) {
        out[(size_t)r * STRIDE] = v[15];
        float cxo = xo, cxi = xi;
        int ro = r - 14, ri = r + 17;
        xo = (ro >= 0) ? in[(size_t)ro * STRIDE] : 0.f;
        xi = (ri < R) ? in[(size_t)ri * STRIDE] : 0.f;

        float dc = (v[30] < cxo) ? v[30] : finf();
#pragma unroll
        for (int i = 30; i >= 1; --i) {
            float dp = (v[i - 1] < cxo) ? v[i - 1] : v[i];
            v[i] = fminf(fmaxf(dp, cxi), dc);
            dc = dp;
        }
        v[0] = fminf(cxi, dc);
    }
}

// ---------------- fused: harmonic (on ST) + percussive (on S) in one launch ------------
__global__ void __launch_bounds__(BS, 6) colmed_fused_kernel(const float* __restrict__ S) {
    if (blockIdx.x < BLOCKS_H) {
        int job = blockIdx.x * BS + threadIdx.x;
        if (job >= NJOBS_H) return;
        const int nCols = CH * HDIM;
        int seg = job / nCols;
        int rem = job - seg * nCols;
        int ch = rem / HDIM;
        int c = rem - ch * HDIM;
        const float* in = g_ST + (size_t)ch * WDIM * STRIDE_T + c;
        float* out = g_harmT + (size_t)ch * WDIM * STRIDE_T + c;
        int r0 = seg * SEG;
        colmed_run<WDIM, STRIDE_T>(in, out, r0, min(r0 + SEG, WDIM));
    } else {
        int job = (blockIdx.x - BLOCKS_H) * BS + threadIdx.x;
        if (job >= NJOBS_P) return;
        const int nCols = CH * WDIM;
        int seg = job / nCols;
        int rem = job - seg * nCols;
        int ch = rem / WDIM;
        int c = rem - ch * WDIM;
        const float* in = S + (size_t)ch * HDIM * WDIM + c;
        float* out = g_perc + (size_t)ch * HDIM * WDIM + c;
        int r0 = seg * SEG;
        colmed_run<HDIM, WDIM>(in, out, r0, min(r0 + SEG, HDIM));
    }
}

// ---------------- mask v2: 32h x 128w tile, float4 gmem, smem de-transpose -------------
// mask_h = h^2/(h^2+p^2); mask_p = p^2/(h^2+p^2)
__global__ void __launch_bounds__(256) mask_kernel(const float4* __restrict__ S4,
                                                   float4* __restrict__ outA,
                                                   float4* __restrict__ outB) {
    __shared__ float tile[128][33];           // [w_local][h_local]
    int ch = blockIdx.z;
    int h0 = blockIdx.y * 32;
    int w0 = blockIdx.x * 128;
    int tx = threadIdx.x, ty = threadIdx.y;   // (32, 8)

    // producer: harmT columns w0..w0+127, rows h0..h0+31 (coalesced along h)
    const float* HT = g_harmT + (size_t)ch * WDIM * STRIDE_T;
    int hcl = min(h0 + tx, STRIDE_T - 1);
#pragma unroll
    for (int wi = 0; wi < 16; ++wi) {
        int wl = ty + 8 * wi;
        tile[wl][tx] = HT[(size_t)(w0 + wl) * STRIDE_T + hcl];
    }
    __syncthreads();

    const float4* P4 = (const float4*)g_perc;
    size_t chOff4 = (size_t)ch * HDIM * (WDIM / 4);
#pragma unroll
    for (int p = 0; p < 4; ++p) {
        int hl = ty + 8 * p;
        int h = h0 + hl;
        if (h < HDIM) {
            size_t idx4 = chOff4 + (size_t)h * (WDIM / 4) + (w0 >> 2) + tx;
            float4 s = S4[idx4];
            float4 pv = P4[idx4];
            float hv0 = tile[4 * tx + 0][hl];
            float hv1 = tile[4 * tx + 1][hl];
            float hv2 = tile[4 * tx + 2][hl];
            float hv3 = tile[4 * tx + 3][hl];
            float4 oa, ob;
            {
                float hh = hv0 * hv0, pp = pv.x * pv.x;
                float rcp = __fdividef(1.0f, fmaxf(hh + pp, 1e-30f));
                oa.x = s.x * hh * rcp; ob.x = s.x * pp * rcp;
            }
            {
                float hh = hv1 * hv1, pp = pv.y * pv.y;
                float rcp = __fdividef(1.0f, fmaxf(hh + pp, 1e-30f));
                oa.y = s.y * hh * rcp; ob.y = s.y * pp * rcp;
            }
            {
                float hh = hv2 * hv2, pp = pv.z * pv.z;
                float rcp = __fdividef(1.0f, fmaxf(hh + pp, 1e-30f));
                oa.z = s.z * hh * rcp; ob.z = s.z * pp * rcp;
            }
            {
                float hh = hv3 * hv3, pp = pv.w * pv.w;
                float rcp = __fdividef(1.0f, fmaxf(hh + pp, 1e-30f));
                oa.w = s.w * hh * rcp; ob.w = s.w * pp * rcp;
            }
            outA[idx4] = oa;
            outB[idx4] = ob;
        }
    }
}

extern "C" void kernel_launch(void* const* d_in, const int* in_sizes, int n_in,
                              void* d_out, int out_size) {
    const float* S = (const float*)d_in[0];
    float* out = (float*)d_out;

    // 1) transpose S into ST (padded stride), 64x64 float4 tiles
    transpose_kernel<<<dim3(WDIM / 64, (HDIM + 63) / 64, CH), 256>>>(S);

    // 2) both median filters in one launch (R5-identical)
    colmed_fused_kernel<<<BLOCKS_H + BLOCKS_P, BS>>>(S);

    // 3) masks + both outputs, vectorized
    mask_kernel<<<dim3(WDIM / 128, (HDIM + 31) / 32, CH), dim3(32, 8)>>>(
        (const float4*)S, (float4*)out, (float4*)(out + NTOT));
}